// round 3
// baseline (speedup 1.0000x reference)
#include <cuda_runtime.h>
#include <cstdint>
#include <cstddef>

#define BB 4
#define NO3 384
#define FFQ 64
#define TTT 512
#define NHH 8
#define HDD 1024
#define CF 8192
#define EPSV 1e-5f

__device__ float g_xt [BB*TTT*CF];
__device__ float g_q  [BB*NHH*TTT*HDD];
__device__ float g_k  [BB*NHH*TTT*HDD];
__device__ float g_v  [BB*NHH*TTT*HDD];
__device__ float g_s  [BB*NHH*TTT*TTT];
__device__ float g_ctx[BB*NHH*TTT*HDD];
__device__ float g_c  [BB*128*TTT*FFQ];
__device__ float g_y  [BB*TTT*CF];
__device__ float g_wq [128*NO3];
__device__ float g_wp [128*128];

// ---- transpose weights to [c][o] ----
__global__ void kW(const float* __restrict__ qw, const float* __restrict__ pw) {
    int i = blockIdx.x * 256 + threadIdx.x;
    if (i < 128*NO3) { int c = i / NO3, o = i % NO3; g_wq[i] = qw[o*128 + c]; }
    if (i < 128*128) { int c = i >> 7,  o = i & 127; g_wp[i] = pw[o*128 + c]; }
}

// ---- x [b][cf][t] -> g_xt [b][t][cf] ----
__global__ void k0(const float* __restrict__ x) {
    __shared__ float tl[32][33];
    int b = blockIdx.z, t0 = blockIdx.x*32, r0 = blockIdx.y*32;
    const float* xb = x + (size_t)b*CF*TTT;
    for (int i = threadIdx.y; i < 32; i += 8)
        tl[i][threadIdx.x] = xb[(size_t)(r0+i)*TTT + t0 + threadIdx.x];
    __syncthreads();
    float* d = g_xt + (size_t)b*TTT*CF;
    for (int i = threadIdx.y; i < 32; i += 8)
        d[(size_t)(t0+i)*CF + r0 + threadIdx.x] = tl[threadIdx.x][i];
}

// ---- QKV conv + PReLU + LN + head scatter; one block per (b,t) ----
__global__ __launch_bounds__(256) void k1(
    const float* __restrict__ bias, const float* __restrict__ alp,
    const float* __restrict__ gam,  const float* __restrict__ bet)
{
    __shared__ float Xs[CF];
    __shared__ float Ws[8*NO3];
    __shared__ float r1[256], r2[256];
    int tid = threadIdx.x, t = blockIdx.x, b = blockIdx.y;
    {
        const float4* s = (const float4*)(g_xt + ((size_t)b*TTT + t)*CF);
        float4* d = (float4*)Xs;
        for (int i = tid; i < CF/4; i += 256) d[i] = s[i];
    }
    int to = tid >> 3, tf = tid & 7;
    float acc[12][8];
    #pragma unroll
    for (int r = 0; r < 12; ++r)
        #pragma unroll
        for (int s = 0; s < 8; ++s) acc[r][s] = 0.f;

    for (int cb = 0; cb < 16; ++cb) {
        __syncthreads();
        {
            const float4* s = (const float4*)(g_wq + cb*8*NO3);
            float4* d = (float4*)Ws;
            for (int i = tid; i < 8*NO3/4; i += 256) d[i] = s[i];
        }
        __syncthreads();
        #pragma unroll
        for (int cc = 0; cc < 8; ++cc) {
            const float* xp = Xs + ((cb*8 + cc) << 6) + (tf << 3);
            float4 x0 = *(const float4*)xp;
            float4 x1 = *(const float4*)(xp + 4);
            const float* wr = Ws + cc*NO3 + to*12;
            #pragma unroll
            for (int r = 0; r < 12; ++r) {
                float w = wr[r];
                acc[r][0] = fmaf(w, x0.x, acc[r][0]);
                acc[r][1] = fmaf(w, x0.y, acc[r][1]);
                acc[r][2] = fmaf(w, x0.z, acc[r][2]);
                acc[r][3] = fmaf(w, x0.w, acc[r][3]);
                acc[r][4] = fmaf(w, x1.x, acc[r][4]);
                acc[r][5] = fmaf(w, x1.y, acc[r][5]);
                acc[r][6] = fmaf(w, x1.z, acc[r][6]);
                acc[r][7] = fmaf(w, x1.w, acc[r][7]);
            }
        }
    }
    float alpha = alp[0];
    float ls = 0.f, lq = 0.f;
    #pragma unroll
    for (int r = 0; r < 12; ++r) {
        float bv = bias[to*12 + r];
        #pragma unroll
        for (int s = 0; s < 8; ++s) {
            float v = acc[r][s] + bv;
            v = v >= 0.f ? v : alpha*v;
            acc[r][s] = v; ls += v; lq += v*v;
        }
    }
    r1[tid] = ls; r2[tid] = lq;
    __syncthreads();
    for (int s = 128; s > 0; s >>= 1) {
        if (tid < s) { r1[tid] += r1[tid+s]; r2[tid] += r2[tid+s]; }
        __syncthreads();
    }
    const float invN = 1.f / (float)(NO3*FFQ);
    float mu = r1[0]*invN, var = r2[0]*invN - mu*mu;
    float rstd = rsqrtf(var + EPSV);
    #pragma unroll
    for (int r = 0; r < 12; ++r) {
        int o = to*12 + r;
        int h = o / 48, rem = o % 48;
        int which = rem >> 4, dc = rem & 15;
        float* dst = (which == 0) ? g_q : (which == 1) ? g_k : g_v;
        size_t base = (((size_t)b*NHH + h)*TTT + t)*HDD + dc*FFQ + (tf << 3);
        int gi = o*FFQ + (tf << 3);
        float ov[8];
        #pragma unroll
        for (int s = 0; s < 8; ++s)
            ov[s] = (acc[r][s] - mu)*rstd*gam[gi + s] + bet[gi + s];
        *(float4*)(dst + base)     = *(float4*)(ov);
        *(float4*)(dst + base + 4) = *(float4*)(ov + 4);
    }
}

// ---- S = Q K^T / 32, causal, 128x128 tiles ----
__global__ __launch_bounds__(256) void k2a() {
    int kt = blockIdx.x, qt = blockIdx.y, bh = blockIdx.z;
    if (kt > qt) return;
    __shared__ float As[16*132], Bs[16*132];
    const float* Qh = g_q + (size_t)bh*TTT*HDD;
    const float* Kh = g_k + (size_t)bh*TTT*HDD;
    int tid = threadIdx.x, tx = tid & 15, ty = tid >> 4;
    float acc[8][8];
    #pragma unroll
    for (int r = 0; r < 8; ++r)
        #pragma unroll
        for (int q = 0; q < 8; ++q) acc[r][q] = 0.f;
    int lrow = tid >> 1, lc = (tid & 1) << 3;
    const float* qp = Qh + (size_t)(qt*128 + lrow)*HDD + lc;
    const float* kp = Kh + (size_t)(kt*128 + lrow)*HDD + lc;
    for (int c0 = 0; c0 < HDD; c0 += 16) {
        __syncthreads();
        float4 a0 = *(const float4*)(qp + c0), a1 = *(const float4*)(qp + c0 + 4);
        float4 b0 = *(const float4*)(kp + c0), b1 = *(const float4*)(kp + c0 + 4);
        As[(lc+0)*132+lrow]=a0.x; As[(lc+1)*132+lrow]=a0.y; As[(lc+2)*132+lrow]=a0.z; As[(lc+3)*132+lrow]=a0.w;
        As[(lc+4)*132+lrow]=a1.x; As[(lc+5)*132+lrow]=a1.y; As[(lc+6)*132+lrow]=a1.z; As[(lc+7)*132+lrow]=a1.w;
        Bs[(lc+0)*132+lrow]=b0.x; Bs[(lc+1)*132+lrow]=b0.y; Bs[(lc+2)*132+lrow]=b0.z; Bs[(lc+3)*132+lrow]=b0.w;
        Bs[(lc+4)*132+lrow]=b1.x; Bs[(lc+5)*132+lrow]=b1.y; Bs[(lc+6)*132+lrow]=b1.z; Bs[(lc+7)*132+lrow]=b1.w;
        __syncthreads();
        #pragma unroll 4
        for (int cc = 0; cc < 16; ++cc) {
            float a[8], bv[8];
            *(float4*)(a)    = *(const float4*)(As + cc*132 + ty*8);
            *(float4*)(a+4)  = *(const float4*)(As + cc*132 + ty*8 + 4);
            *(float4*)(bv)   = *(const float4*)(Bs + cc*132 + tx*8);
            *(float4*)(bv+4) = *(const float4*)(Bs + cc*132 + tx*8 + 4);
            #pragma unroll
            for (int r = 0; r < 8; ++r)
                #pragma unroll
                for (int q = 0; q < 8; ++q)
                    acc[r][q] = fmaf(a[r], bv[q], acc[r][q]);
        }
    }
    float* S = g_s + (size_t)bh*TTT*TTT;
    #pragma unroll
    for (int r = 0; r < 8; ++r) {
        int qi = qt*128 + ty*8 + r, k0 = kt*128 + tx*8;
        float ov[8];
        #pragma unroll
        for (int q = 0; q < 8; ++q)
            ov[q] = ((k0 + q) <= qi) ? acc[r][q]*0.03125f : -1e30f;
        *(float4*)(S + (size_t)qi*TTT + k0)     = *(float4*)(ov);
        *(float4*)(S + (size_t)qi*TTT + k0 + 4) = *(float4*)(ov + 4);
    }
}

// ---- prefix softmax per row ----
__global__ __launch_bounds__(256) void k2b() {
    int qi = blockIdx.x, bh = blockIdx.y;
    int n = (qi & ~127) + 128;
    float* row = g_s + ((size_t)bh*TTT + qi)*TTT;
    __shared__ float red[256];
    int tid = threadIdx.x;
    float v0 = (tid < n)     ? row[tid]     : -1e30f;
    float v1 = (tid+256 < n) ? row[tid+256] : -1e30f;
    red[tid] = fmaxf(v0, v1); __syncthreads();
    for (int s = 128; s > 0; s >>= 1) {
        if (tid < s) red[tid] = fmaxf(red[tid], red[tid+s]);
        __syncthreads();
    }
    float m = red[0]; __syncthreads();
    float e0 = __expf(v0 - m), e1 = __expf(v1 - m);
    red[tid] = e0 + e1; __syncthreads();
    for (int s = 128; s > 0; s >>= 1) {
        if (tid < s) red[tid] += red[tid+s];
        __syncthreads();
    }
    float inv = 1.f / red[0];
    if (tid < n)     row[tid]     = e0*inv;
    if (tid+256 < n) row[tid+256] = e1*inv;
}

// ---- ctx = P @ V ----
__global__ __launch_bounds__(256) void k2c() {
    int dt = blockIdx.x, qt = blockIdx.y, bh = blockIdx.z;
    __shared__ float As[16*132], Bs[16*128];
    const float* P = g_s + (size_t)bh*TTT*TTT;
    const float* V = g_v + (size_t)bh*TTT*HDD;
    int tid = threadIdx.x, tx = tid & 15, ty = tid >> 4;
    float acc[8][8];
    #pragma unroll
    for (int r = 0; r < 8; ++r)
        #pragma unroll
        for (int q = 0; q < 8; ++q) acc[r][q] = 0.f;
    int arow = tid >> 1, ac = (tid & 1) << 3;
    int brow = tid >> 4, bc = (tid & 15) << 3;
    int kmax = (qt + 1)*128;
    const float* pp = P + (size_t)(qt*128 + arow)*TTT + ac;
    const float* vp = V + (size_t)dt*128 + bc;
    for (int k0 = 0; k0 < kmax; k0 += 16) {
        __syncthreads();
        float4 a0 = *(const float4*)(pp + k0), a1 = *(const float4*)(pp + k0 + 4);
        As[(ac+0)*132+arow]=a0.x; As[(ac+1)*132+arow]=a0.y; As[(ac+2)*132+arow]=a0.z; As[(ac+3)*132+arow]=a0.w;
        As[(ac+4)*132+arow]=a1.x; As[(ac+5)*132+arow]=a1.y; As[(ac+6)*132+arow]=a1.z; As[(ac+7)*132+arow]=a1.w;
        float4 b0 = *(const float4*)(vp + (size_t)(k0+brow)*HDD);
        float4 b1 = *(const float4*)(vp + (size_t)(k0+brow)*HDD + 4);
        *(float4*)(Bs + brow*128 + bc)     = b0;
        *(float4*)(Bs + brow*128 + bc + 4) = b1;
        __syncthreads();
        #pragma unroll 4
        for (int cc = 0; cc < 16; ++cc) {
            float a[8], bv[8];
            *(float4*)(a)    = *(const float4*)(As + cc*132 + ty*8);
            *(float4*)(a+4)  = *(const float4*)(As + cc*132 + ty*8 + 4);
            *(float4*)(bv)   = *(const float4*)(Bs + cc*128 + tx*8);
            *(float4*)(bv+4) = *(const float4*)(Bs + cc*128 + tx*8 + 4);
            #pragma unroll
            for (int r = 0; r < 8; ++r)
                #pragma unroll
                for (int q = 0; q < 8; ++q)
                    acc[r][q] = fmaf(a[r], bv[q], acc[r][q]);
        }
    }
    float* C = g_ctx + (size_t)bh*TTT*HDD;
    #pragma unroll
    for (int r = 0; r < 8; ++r) {
        size_t o = (size_t)(qt*128 + ty*8 + r)*HDD + dt*128 + tx*8;
        *(float4*)(C + o)     = *(float4*)(acc[r]);
        *(float4*)(C + o + 4) = *(float4*)(acc[r] + 4);
    }
}

// ---- ctx remap: per (bh,dc) transpose [512 t][64 df] -> [64 df][512 t] ----
__global__ void k3() {
    __shared__ float tl[32][33];
    int bhdc = blockIdx.z, bh = bhdc >> 4, dc = bhdc & 15;
    int t0 = blockIdx.x*32, d0 = blockIdx.y*32;
    const float* src = g_ctx + (size_t)bh*TTT*HDD + dc*64;
    for (int i = threadIdx.y; i < 32; i += 8)
        tl[i][threadIdx.x] = src[(size_t)(t0+i)*HDD + d0 + threadIdx.x];
    __syncthreads();
    float* dst = g_c + (size_t)bhdc*TTT*FFQ;
    for (int i = threadIdx.y; i < 32; i += 8)
        dst[(size_t)(d0+i)*TTT + t0 + threadIdx.x] = tl[threadIdx.x][i];
}

// ---- proj conv + PReLU + LN; one block per (b,t2) ----
__global__ __launch_bounds__(256) void k4(
    const float* __restrict__ bias, const float* __restrict__ alp,
    const float* __restrict__ gam,  const float* __restrict__ bet)
{
    __shared__ float Xs[CF];
    __shared__ float Ws[8*128];
    __shared__ float r1[256], r2[256];
    int tid = threadIdx.x, t2 = blockIdx.x, b = blockIdx.y;
    for (int i = tid; i < 2048; i += 256) {
        int c = i >> 4, f4 = i & 15;
        ((float4*)Xs)[i] = *(const float4*)(g_c + ((((size_t)(b*128 + c))*TTT + t2) << 6) + f4*4);
    }
    int to = tid >> 3, tf = tid & 7;
    float acc[4][8];
    #pragma unroll
    for (int r = 0; r < 4; ++r)
        #pragma unroll
        for (int s = 0; s < 8; ++s) acc[r][s] = 0.f;
    for (int cb = 0; cb < 16; ++cb) {
        __syncthreads();
        for (int i = tid; i < 256; i += 256)
            ((float4*)Ws)[i] = ((const float4*)(g_wp + cb*1024))[i];
        __syncthreads();
        #pragma unroll
        for (int cc = 0; cc < 8; ++cc) {
            const float* xp = Xs + ((cb*8 + cc) << 6) + (tf << 3);
            float4 x0 = *(const float4*)xp;
            float4 x1 = *(const float4*)(xp + 4);
            const float* wr = Ws + cc*128 + to*4;
            #pragma unroll
            for (int r = 0; r < 4; ++r) {
                float w = wr[r];
                acc[r][0] = fmaf(w, x0.x, acc[r][0]);
                acc[r][1] = fmaf(w, x0.y, acc[r][1]);
                acc[r][2] = fmaf(w, x0.z, acc[r][2]);
                acc[r][3] = fmaf(w, x0.w, acc[r][3]);
                acc[r][4] = fmaf(w, x1.x, acc[r][4]);
                acc[r][5] = fmaf(w, x1.y, acc[r][5]);
                acc[r][6] = fmaf(w, x1.z, acc[r][6]);
                acc[r][7] = fmaf(w, x1.w, acc[r][7]);
            }
        }
    }
    float alpha = alp[0];
    float ls = 0.f, lq = 0.f;
    #pragma unroll
    for (int r = 0; r < 4; ++r) {
        float bv = bias[to*4 + r];
        #pragma unroll
        for (int s = 0; s < 8; ++s) {
            float v = acc[r][s] + bv;
            v = v >= 0.f ? v : alpha*v;
            acc[r][s] = v; ls += v; lq += v*v;
        }
    }
    r1[tid] = ls; r2[tid] = lq;
    __syncthreads();
    for (int s = 128; s > 0; s >>= 1) {
        if (tid < s) { r1[tid] += r1[tid+s]; r2[tid] += r2[tid+s]; }
        __syncthreads();
    }
    const float invN = 1.f / (float)CF;
    float mu = r1[0]*invN, var = r2[0]*invN - mu*mu;
    float rstd = rsqrtf(var + EPSV);
    float* yrow = g_y + ((size_t)b*TTT + t2)*CF;
    #pragma unroll
    for (int r = 0; r < 4; ++r) {
        int o = to*4 + r;
        int gi = o*FFQ + (tf << 3);
        float ov[8];
        #pragma unroll
        for (int s = 0; s < 8; ++s)
            ov[s] = (acc[r][s] - mu)*rstd*gam[gi + s] + bet[gi + s];
        *(float4*)(yrow + gi)     = *(float4*)(ov);
        *(float4*)(yrow + gi + 4) = *(float4*)(ov + 4);
    }
}

// ---- g_y [b][t2][cf] -> out [b][cf][t2] ----
__global__ void k5(float* __restrict__ out) {
    __shared__ float tl[32][33];
    int b = blockIdx.z, t0 = blockIdx.x*32, r0 = blockIdx.y*32;
    const float* s = g_y + (size_t)b*TTT*CF;
    for (int i = threadIdx.y; i < 32; i += 8)
        tl[i][threadIdx.x] = s[(size_t)(t0+i)*CF + r0 + threadIdx.x];
    __syncthreads();
    float* d = out + (size_t)b*CF*TTT;
    for (int i = threadIdx.y; i < 32; i += 8)
        d[(size_t)(r0+i)*TTT + t0 + threadIdx.x] = tl[threadIdx.x][i];
}

extern "C" void kernel_launch(void* const* d_in, const int* in_sizes, int n_in,
                              void* d_out, int out_size) {
    const float* x   = (const float*)d_in[0];
    const float* qw  = (const float*)d_in[1];
    const float* qb  = (const float*)d_in[2];
    const float* qa  = (const float*)d_in[3];
    const float* qg  = (const float*)d_in[4];
    const float* qbe = (const float*)d_in[5];
    const float* pw  = (const float*)d_in[6];
    const float* pb  = (const float*)d_in[7];
    const float* pa  = (const float*)d_in[8];
    const float* pg  = (const float*)d_in[9];
    const float* pbe = (const float*)d_in[10];
    float* out = (float*)d_out;

    dim3 tb(32, 8);
    kW <<<192, 256>>>(qw, pw);
    k0 <<<dim3(16, 256, 4), tb>>>(x);
    k1 <<<dim3(512, 4), 256>>>(qb, qa, qg, qbe);
    k2a<<<dim3(4, 4, 32), 256>>>();
    k2b<<<dim3(512, 32), 256>>>();
    k2c<<<dim3(8, 4, 32), 256>>>();
    k3 <<<dim3(16, 2, 512), tb>>>();
    k4 <<<dim3(512, 4), 256>>>(pb, pa, pg, pbe);
    k5 <<<dim3(16, 256, 4), tb>>>(out);
}

// round 6
// speedup vs baseline: 1.3085x; 1.3085x over previous
#include <cuda_runtime.h>
#include <cuda_bf16.h>
#include <cstdint>
#include <cstddef>

#define BB 4
#define NO3 384
#define FFQ 64
#define TTT 512
#define NHH 8
#define HDD 1024
#define CF 8192
#define EPSV 1e-5f

// ---------------- scratch ----------------
__device__ float g_xt [BB*TTT*CF];
__device__ float g_v  [BB*NHH*TTT*HDD];
__device__ float g_s  [BB*NHH*TTT*TTT];
__device__ float g_ctx[BB*NHH*TTT*HDD];
__device__ float g_c  [BB*128*TTT*FFQ];
__device__ float g_y  [BB*TTT*CF];
__device__ float g_wq [128*NO3];
__device__ float g_wp [128*128];
__device__ __nv_bfloat16 g_qh[BB*NHH*TTT*HDD];
__device__ __nv_bfloat16 g_ql[BB*NHH*TTT*HDD];
__device__ __nv_bfloat16 g_kh[BB*NHH*TTT*HDD];
__device__ __nv_bfloat16 g_kl[BB*NHH*TTT*HDD];
__device__ __nv_bfloat16 g_vth[BB*NHH*HDD*TTT];
__device__ __nv_bfloat16 g_vtl[BB*NHH*HDD*TTT];
__device__ __nv_bfloat16 g_ph[BB*NHH*TTT*TTT];
__device__ __nv_bfloat16 g_pl[BB*NHH*TTT*TTT];

// ---------------- warp-mma helpers ----------------
__device__ __forceinline__ uint32_t smem_u32(const void* p) {
    uint32_t a;
    asm("{ .reg .u64 t; cvta.to.shared.u64 t, %1; cvt.u32.u64 %0, t; }" : "=r"(a) : "l"(p));
    return a;
}
__device__ __forceinline__ void ldsm4(uint32_t* r, uint32_t a) {
    asm volatile("ldmatrix.sync.aligned.m8n8.x4.shared.b16 {%0,%1,%2,%3}, [%4];"
        : "=r"(r[0]), "=r"(r[1]), "=r"(r[2]), "=r"(r[3]) : "r"(a));
}
__device__ __forceinline__ void mmabf(float* c, const uint32_t* a, const uint32_t* b) {
    asm volatile("mma.sync.aligned.m16n8k16.row.col.f32.bf16.bf16.f32 "
        "{%0,%1,%2,%3}, {%4,%5,%6,%7}, {%8,%9}, {%0,%1,%2,%3};"
        : "+f"(c[0]), "+f"(c[1]), "+f"(c[2]), "+f"(c[3])
        : "r"(a[0]), "r"(a[1]), "r"(a[2]), "r"(a[3]), "r"(b[0]), "r"(b[1]));
}

// smem tile: 128 rows x 64 cols bf16, row stride 72 elems (144B, 16B-aligned rows)
#define SROW 72
#define STILE (128*SROW)
#define SMEMSZ (4*STILE*2)

// C[128,128] += (Ah+Al)(Bh+Bl)^T over k in [0,kmax)
template<bool MASK>
__device__ __forceinline__ void mma_core(
    const __nv_bfloat16* __restrict__ Ah, const __nv_bfloat16* __restrict__ Al, int lda,
    const __nv_bfloat16* __restrict__ Bh, const __nv_bfloat16* __restrict__ Bl, int ldb,
    int kmax, float* __restrict__ outp, int ldo, int row0, int col0, float scale)
{
    extern __shared__ __align__(16) __nv_bfloat16 sm[];
    __nv_bfloat16* sAh = sm;
    __nv_bfloat16* sAl = sm + STILE;
    __nv_bfloat16* sBh = sm + 2*STILE;
    __nv_bfloat16* sBl = sm + 3*STILE;
    uint32_t uAh = smem_u32(sAh), uAl = smem_u32(sAl);
    uint32_t uBh = smem_u32(sBh), uBl = smem_u32(sBl);

    int tid = threadIdx.x, lane = tid & 31, wid = tid >> 5;
    int wm = wid >> 2, wn = wid & 3;

    float acc[4][4][4];
    #pragma unroll
    for (int i = 0; i < 4; ++i)
        #pragma unroll
        for (int j = 0; j < 4; ++j)
            #pragma unroll
            for (int q = 0; q < 4; ++q) acc[i][j][q] = 0.f;

    uint32_t aoff = (uint32_t)(((wm*64 + (lane & 15))*SROW + (lane >> 4)*8) * 2);
    uint32_t boff = (uint32_t)(((wn*32 + ((lane & 7) + ((lane >> 4) << 3)))*SROW + ((lane >> 3) & 1)*8) * 2);

    for (int k0 = 0; k0 < kmax; k0 += 64) {
        __syncthreads();
        #pragma unroll
        for (int j = 0; j < 4; ++j) {
            int ii = j*256 + tid;
            int r = ii >> 3, c = (ii & 7) << 3;
            *(uint4*)(sAh + r*SROW + c) = *(const uint4*)(Ah + (size_t)r*lda + k0 + c);
            *(uint4*)(sAl + r*SROW + c) = *(const uint4*)(Al + (size_t)r*lda + k0 + c);
            *(uint4*)(sBh + r*SROW + c) = *(const uint4*)(Bh + (size_t)r*ldb + k0 + c);
            *(uint4*)(sBl + r*SROW + c) = *(const uint4*)(Bl + (size_t)r*ldb + k0 + c);
        }
        __syncthreads();
        #pragma unroll
        for (int kk = 0; kk < 4; ++kk) {
            uint32_t bh[4][2], bl[4][2];
            #pragma unroll
            for (int ng = 0; ng < 2; ++ng) {
                uint32_t r4[4];
                ldsm4(r4, uBh + boff + ng*(16*SROW*2) + kk*32);
                bh[ng*2][0] = r4[0]; bh[ng*2][1] = r4[1];
                bh[ng*2+1][0] = r4[2]; bh[ng*2+1][1] = r4[3];
                ldsm4(r4, uBl + boff + ng*(16*SROW*2) + kk*32);
                bl[ng*2][0] = r4[0]; bl[ng*2][1] = r4[1];
                bl[ng*2+1][0] = r4[2]; bl[ng*2+1][1] = r4[3];
            }
            #pragma unroll
            for (int mf = 0; mf < 4; ++mf) {
                uint32_t ah[4], al[4];
                ldsm4(ah, uAh + aoff + mf*(16*SROW*2) + kk*32);
                ldsm4(al, uAl + aoff + mf*(16*SROW*2) + kk*32);
                #pragma unroll
                for (int nf = 0; nf < 4; ++nf) {
                    mmabf(acc[mf][nf], ah, bh[nf]);
                    mmabf(acc[mf][nf], ah, bl[nf]);
                    mmabf(acc[mf][nf], al, bh[nf]);
                }
            }
        }
    }

    // epilogue: store at LOCAL row, mask with GLOBAL row/col
    int rloc0 = wm*64 + (lane >> 2);
    int cloc  = wn*32 + (lane & 3)*2;
    #pragma unroll
    for (int mf = 0; mf < 4; ++mf) {
        #pragma unroll
        for (int nf = 0; nf < 4; ++nf) {
            int cc = cloc + nf*8;
            int cg = col0 + cc;
            #pragma unroll
            for (int h = 0; h < 2; ++h) {
                int rl = rloc0 + mf*16 + h*8;
                int rg = row0 + rl;
                float v0 = acc[mf][nf][2*h], v1 = acc[mf][nf][2*h+1];
                if (MASK) {
                    v0 = (cg     <= rg) ? v0*scale : -1e30f;
                    v1 = (cg + 1 <= rg) ? v1*scale : -1e30f;
                }
                *(float2*)(outp + (size_t)rl*ldo + cc) = make_float2(v0, v1);
            }
        }
    }
}

// ---- transpose weights to [c][o] ----
__global__ void kW(const float* __restrict__ qw, const float* __restrict__ pw) {
    int i = blockIdx.x * 256 + threadIdx.x;
    if (i < 128*NO3) { int c = i / NO3, o = i % NO3; g_wq[i] = qw[o*128 + c]; }
    if (i < 128*128) { int c = i >> 7,  o = i & 127; g_wp[i] = pw[o*128 + c]; }
}

// ---- x [b][cf][t] -> g_xt [b][t][cf] ----
__global__ void k0(const float* __restrict__ x) {
    __shared__ float tl[32][33];
    int b = blockIdx.z, t0 = blockIdx.x*32, r0 = blockIdx.y*32;
    const float* xb = x + (size_t)b*CF*TTT;
    for (int i = threadIdx.y; i < 32; i += 8)
        tl[i][threadIdx.x] = xb[(size_t)(r0+i)*TTT + t0 + threadIdx.x];
    __syncthreads();
    float* d = g_xt + (size_t)b*TTT*CF;
    for (int i = threadIdx.y; i < 32; i += 8)
        d[(size_t)(t0+i)*CF + r0 + threadIdx.x] = tl[threadIdx.x][i];
}

// ---- QKV conv + PReLU + LN + head scatter ----
__global__ __launch_bounds__(256) void k1(
    const float* __restrict__ bias, const float* __restrict__ alp,
    const float* __restrict__ gam,  const float* __restrict__ bet)
{
    __shared__ float Xs[CF];
    __shared__ float Ws[8*NO3];
    __shared__ float r1[256], r2[256];
    int tid = threadIdx.x, t = blockIdx.x, b = blockIdx.y;
    {
        const float4* s = (const float4*)(g_xt + ((size_t)b*TTT + t)*CF);
        float4* d = (float4*)Xs;
        for (int i = tid; i < CF/4; i += 256) d[i] = s[i];
    }
    int to = tid >> 3, tf = tid & 7;
    float acc[12][8];
    #pragma unroll
    for (int r = 0; r < 12; ++r)
        #pragma unroll
        for (int s = 0; s < 8; ++s) acc[r][s] = 0.f;

    for (int cb = 0; cb < 16; ++cb) {
        __syncthreads();
        {
            const float4* s = (const float4*)(g_wq + cb*8*NO3);
            float4* d = (float4*)Ws;
            for (int i = tid; i < 8*NO3/4; i += 256) d[i] = s[i];
        }
        __syncthreads();
        #pragma unroll
        for (int cc = 0; cc < 8; ++cc) {
            const float* xp = Xs + ((cb*8 + cc) << 6) + (tf << 3);
            float4 x0 = *(const float4*)xp;
            float4 x1 = *(const float4*)(xp + 4);
            const float* wr = Ws + cc*NO3 + to*12;
            float4 wa = *(const float4*)(wr);
            float4 wb = *(const float4*)(wr + 4);
            float4 wc = *(const float4*)(wr + 8);
            float wv[12] = {wa.x,wa.y,wa.z,wa.w, wb.x,wb.y,wb.z,wb.w, wc.x,wc.y,wc.z,wc.w};
            #pragma unroll
            for (int r = 0; r < 12; ++r) {
                float w = wv[r];
                acc[r][0] = fmaf(w, x0.x, acc[r][0]);
                acc[r][1] = fmaf(w, x0.y, acc[r][1]);
                acc[r][2] = fmaf(w, x0.z, acc[r][2]);
                acc[r][3] = fmaf(w, x0.w, acc[r][3]);
                acc[r][4] = fmaf(w, x1.x, acc[r][4]);
                acc[r][5] = fmaf(w, x1.y, acc[r][5]);
                acc[r][6] = fmaf(w, x1.z, acc[r][6]);
                acc[r][7] = fmaf(w, x1.w, acc[r][7]);
            }
        }
    }
    float alpha = alp[0];
    float ls = 0.f, lq = 0.f;
    #pragma unroll
    for (int r = 0; r < 12; ++r) {
        float bv = bias[to*12 + r];
        #pragma unroll
        for (int s = 0; s < 8; ++s) {
            float v = acc[r][s] + bv;
            v = v >= 0.f ? v : alpha*v;
            acc[r][s] = v; ls += v; lq += v*v;
        }
    }
    r1[tid] = ls; r2[tid] = lq;
    __syncthreads();
    for (int s = 128; s > 0; s >>= 1) {
        if (tid < s) { r1[tid] += r1[tid+s]; r2[tid] += r2[tid+s]; }
        __syncthreads();
    }
    const float invN = 1.f / (float)(NO3*FFQ);
    float mu = r1[0]*invN, var = r2[0]*invN - mu*mu;
    float rstd = rsqrtf(var + EPSV);
    #pragma unroll
    for (int r = 0; r < 12; ++r) {
        int o = to*12 + r;
        int h = o / 48, rem = o % 48;
        int which = rem >> 4, dc = rem & 15;
        size_t base = (((size_t)b*NHH + h)*TTT + t)*HDD + dc*FFQ + (tf << 3);
        int gi = o*FFQ + (tf << 3);
        float ov[8];
        #pragma unroll
        for (int s = 0; s < 8; ++s)
            ov[s] = (acc[r][s] - mu)*rstd*gam[gi + s] + bet[gi + s];
        if (which == 2) {
            *(float4*)(g_v + base)     = *(float4*)(ov);
            *(float4*)(g_v + base + 4) = *(float4*)(ov + 4);
        } else {
            __nv_bfloat16* dh = (which == 0) ? g_qh : g_kh;
            __nv_bfloat16* dl = (which == 0) ? g_ql : g_kl;
            uint32_t hp[4], lp[4];
            #pragma unroll
            for (int p = 0; p < 4; ++p) {
                float f0 = ov[2*p], f1 = ov[2*p+1];
                __nv_bfloat16 h0 = __float2bfloat16(f0);
                __nv_bfloat16 h1 = __float2bfloat16(f1);
                __nv_bfloat16 l0 = __float2bfloat16(f0 - __bfloat162float(h0));
                __nv_bfloat16 l1 = __float2bfloat16(f1 - __bfloat162float(h1));
                hp[p] = (uint32_t)__bfloat16_as_ushort(h0) | ((uint32_t)__bfloat16_as_ushort(h1) << 16);
                lp[p] = (uint32_t)__bfloat16_as_ushort(l0) | ((uint32_t)__bfloat16_as_ushort(l1) << 16);
            }
            *(uint4*)(dh + base) = *(uint4*)hp;
            *(uint4*)(dl + base) = *(uint4*)lp;
        }
    }
}

// ---- V transpose + split ----
__global__ void k1v() {
    __shared__ float tl[32][33];
    int bh = blockIdx.z, t0 = blockIdx.x*32, d0 = blockIdx.y*32;
    const float* src = g_v + (size_t)bh*TTT*HDD;
    for (int i = threadIdx.y; i < 32; i += 8)
        tl[i][threadIdx.x] = src[(size_t)(t0+i)*HDD + d0 + threadIdx.x];
    __syncthreads();
    size_t ob = (size_t)bh*HDD*TTT;
    for (int i = threadIdx.y; i < 32; i += 8) {
        float f = tl[threadIdx.x][i];
        __nv_bfloat16 h = __float2bfloat16(f);
        __nv_bfloat16 l = __float2bfloat16(f - __bfloat162float(h));
        size_t o = ob + (size_t)(d0+i)*TTT + t0 + threadIdx.x;
        g_vth[o] = h; g_vtl[o] = l;
    }
}

// ---- k2a: S = QK^T /32 (causal) ----
__global__ __launch_bounds__(256) void k2a() {
    int kt = blockIdx.x, qt = blockIdx.y, bh = blockIdx.z;
    if (kt > qt) return;
    const __nv_bfloat16* Ah = g_qh + ((size_t)bh*TTT + qt*128)*HDD;
    const __nv_bfloat16* Al = g_ql + ((size_t)bh*TTT + qt*128)*HDD;
    const __nv_bfloat16* Bh = g_kh + ((size_t)bh*TTT + kt*128)*HDD;
    const __nv_bfloat16* Bl = g_kl + ((size_t)bh*TTT + kt*128)*HDD;
    float* outp = g_s + (size_t)bh*TTT*TTT + (size_t)(qt*128)*TTT + kt*128;
    mma_core<true>(Ah, Al, HDD, Bh, Bl, HDD, HDD, outp, TTT, qt*128, kt*128, 0.03125f);
}

// ---- k2b: prefix softmax -> P hi/lo bf16 ----
__global__ __launch_bounds__(256) void k2b() {
    int qi = blockIdx.x, bh = blockIdx.y;
    int n = (qi & ~127) + 128;
    const float* row = g_s + ((size_t)bh*TTT + qi)*TTT;
    __shared__ float red[256];
    int tid = threadIdx.x;
    float v0 = (tid < n)     ? row[tid]     : -1e30f;
    float v1 = (tid+256 < n) ? row[tid+256] : -1e30f;
    red[tid] = fmaxf(v0, v1); __syncthreads();
    for (int s = 128; s > 0; s >>= 1) {
        if (tid < s) red[tid] = fmaxf(red[tid], red[tid+s]);
        __syncthreads();
    }
    float m = red[0]; __syncthreads();
    float e0 = __expf(v0 - m), e1 = __expf(v1 - m);
    red[tid] = e0 + e1; __syncthreads();
    for (int s = 128; s > 0; s >>= 1) {
        if (tid < s) red[tid] += red[tid+s];
        __syncthreads();
    }
    float inv = 1.f / red[0];
    __nv_bfloat16* ph = g_ph + ((size_t)bh*TTT + qi)*TTT;
    __nv_bfloat16* pl = g_pl + ((size_t)bh*TTT + qi)*TTT;
    if (tid < n) {
        float p = e0 * inv;
        __nv_bfloat16 h = __float2bfloat16(p);
        ph[tid] = h; pl[tid] = __float2bfloat16(p - __bfloat162float(h));
    }
    if (tid + 256 < n) {
        float p = e1 * inv;
        __nv_bfloat16 h = __float2bfloat16(p);
        ph[tid+256] = h; pl[tid+256] = __float2bfloat16(p - __bfloat162float(h));
    }
}

// ---- k2c: ctx = P @ V ----
__global__ __launch_bounds__(256) void k2c() {
    int dt = blockIdx.x, qt = blockIdx.y, bh = blockIdx.z;
    const __nv_bfloat16* Ah = g_ph  + ((size_t)bh*TTT + qt*128)*TTT;
    const __nv_bfloat16* Al = g_pl  + ((size_t)bh*TTT + qt*128)*TTT;
    const __nv_bfloat16* Bh = g_vth + ((size_t)bh*HDD + dt*128)*TTT;
    const __nv_bfloat16* Bl = g_vtl + ((size_t)bh*HDD + dt*128)*TTT;
    float* outp = g_ctx + (size_t)bh*TTT*HDD + (size_t)(qt*128)*HDD + dt*128;
    mma_core<false>(Ah, Al, TTT, Bh, Bl, TTT, (qt + 1)*128, outp, HDD, 0, 0, 1.f);
}

// ---- ctx remap ----
__global__ void k3() {
    __shared__ float tl[32][33];
    int bhdc = blockIdx.z, bh = bhdc >> 4, dc = bhdc & 15;
    int t0 = blockIdx.x*32, d0 = blockIdx.y*32;
    const float* src = g_ctx + (size_t)bh*TTT*HDD + dc*64;
    for (int i = threadIdx.y; i < 32; i += 8)
        tl[i][threadIdx.x] = src[(size_t)(t0+i)*HDD + d0 + threadIdx.x];
    __syncthreads();
    float* dst = g_c + (size_t)bhdc*TTT*FFQ;
    for (int i = threadIdx.y; i < 32; i += 8)
        dst[(size_t)(d0+i)*TTT + t0 + threadIdx.x] = tl[threadIdx.x][i];
}

// ---- proj conv + PReLU + LN ----
__global__ __launch_bounds__(256) void k4(
    const float* __restrict__ bias, const float* __restrict__ alp,
    const float* __restrict__ gam,  const float* __restrict__ bet)
{
    __shared__ float Xs[CF];
    __shared__ float Ws[8*128];
    __shared__ float r1[256], r2[256];
    int tid = threadIdx.x, t2 = blockIdx.x, b = blockIdx.y;
    for (int i = tid; i < 2048; i += 256) {
        int c = i >> 4, f4 = i & 15;
        ((float4*)Xs)[i] = *(const float4*)(g_c + ((((size_t)(b*128 + c))*TTT + t2) << 6) + f4*4);
    }
    int to = tid >> 3, tf = tid & 7;
    float acc[4][8];
    #pragma unroll
    for (int r = 0; r < 4; ++r)
        #pragma unroll
        for (int s = 0; s < 8; ++s) acc[r][s] = 0.f;
    for (int cb = 0; cb < 16; ++cb) {
        __syncthreads();
        for (int i = tid; i < 256; i += 256)
            ((float4*)Ws)[i] = ((const float4*)(g_wp + cb*1024))[i];
        __syncthreads();
        #pragma unroll
        for (int cc = 0; cc < 8; ++cc) {
            const float* xp = Xs + ((cb*8 + cc) << 6) + (tf << 3);
            float4 x0 = *(const float4*)xp;
            float4 x1 = *(const float4*)(xp + 4);
            float4 wq4 = *(const float4*)(Ws + cc*128 + to*4);
            float wv[4] = {wq4.x, wq4.y, wq4.z, wq4.w};
            #pragma unroll
            for (int r = 0; r < 4; ++r) {
                float w = wv[r];
                acc[r][0] = fmaf(w, x0.x, acc[r][0]);
                acc[r][1] = fmaf(w, x0.y, acc[r][1]);
                acc[r][2] = fmaf(w, x0.z, acc[r][2]);
                acc[r][3] = fmaf(w, x0.w, acc[r][3]);
                acc[r][4] = fmaf(w, x1.x, acc[r][4]);
                acc[r][5] = fmaf(w, x1.y, acc[r][5]);
                acc[r][6] = fmaf(w, x1.z, acc[r][6]);
                acc[r][7] = fmaf(w, x1.w, acc[r][7]);
            }
        }
    }
    float alpha = alp[0];
    float ls = 0.f, lq = 0.f;
    #pragma unroll
    for (int r = 0; r < 4; ++r) {
        float bv = bias[to*4 + r];
        #pragma unroll
        for (int s = 0; s < 8; ++s) {
            float v = acc[r][s] + bv;
            v = v >= 0.f ? v : alpha*v;
            acc[r][s] = v; ls += v; lq += v*v;
        }
    }
    r1[tid] = ls; r2[tid] = lq;
    __syncthreads();
    for (int s = 128; s > 0; s >>= 1) {
        if (tid < s) { r1[tid] += r1[tid+s]; r2[tid] += r2[tid+s]; }
        __syncthreads();
    }
    const float invN = 1.f / (float)CF;
    float mu = r1[0]*invN, var = r2[0]*invN - mu*mu;
    float rstd = rsqrtf(var + EPSV);
    float* yrow = g_y + ((size_t)b*TTT + t2)*CF;
    #pragma unroll
    for (int r = 0; r < 4; ++r) {
        int o = to*4 + r;
        int gi = o*FFQ + (tf << 3);
        float ov[8];
        #pragma unroll
        for (int s = 0; s < 8; ++s)
            ov[s] = (acc[r][s] - mu)*rstd*gam[gi + s] + bet[gi + s];
        *(float4*)(yrow + gi)     = *(float4*)(ov);
        *(float4*)(yrow + gi + 4) = *(float4*)(ov + 4);
    }
}

// ---- g_y [b][t2][cf] -> out [b][cf][t2] ----
__global__ void k5(float* __restrict__ out) {
    __shared__ float tl[32][33];
    int b = blockIdx.z, t0 = blockIdx.x*32, r0 = blockIdx.y*32;
    const float* s = g_y + (size_t)b*TTT*CF;
    for (int i = threadIdx.y; i < 32; i += 8)
        tl[i][threadIdx.x] = s[(size_t)(t0+i)*CF + r0 + threadIdx.x];
    __syncthreads();
    float* d = out + (size_t)b*CF*TTT;
    for (int i = threadIdx.y; i < 32; i += 8)
        d[(size_t)(r0+i)*TTT + t0 + threadIdx.x] = tl[threadIdx.x][i];
}

extern "C" void kernel_launch(void* const* d_in, const int* in_sizes, int n_in,
                              void* d_out, int out_size) {
    const float* x   = (const float*)d_in[0];
    const float* qw  = (const float*)d_in[1];
    const float* qb  = (const float*)d_in[2];
    const float* qa  = (const float*)d_in[3];
    const float* qg  = (const float*)d_in[4];
    const float* qbe = (const float*)d_in[5];
    const float* pw  = (const float*)d_in[6];
    const float* pb  = (const float*)d_in[7];
    const float* pa  = (const float*)d_in[8];
    const float* pg  = (const float*)d_in[9];
    const float* pbe = (const float*)d_in[10];
    float* out = (float*)d_out;

    cudaFuncSetAttribute(k2a, cudaFuncAttributeMaxDynamicSharedMemorySize, SMEMSZ);
    cudaFuncSetAttribute(k2c, cudaFuncAttributeMaxDynamicSharedMemorySize, SMEMSZ);

    dim3 tb(32, 8);
    kW <<<192, 256>>>(qw, pw);
    k0 <<<dim3(16, 256, 4), tb>>>(x);
    k1 <<<dim3(512, 4), 256>>>(qb, qa, qg, qbe);
    k1v<<<dim3(16, 32, 32), tb>>>();
    k2a<<<dim3(4, 4, 32), 256, SMEMSZ>>>();
    k2b<<<dim3(512, 32), 256>>>();
    k2c<<<dim3(8, 4, 32), 256, SMEMSZ>>>();
    k3 <<<dim3(16, 2, 512), tb>>>();
    k4 <<<dim3(512, 4), 256>>>(pb, pa, pg, pbe);
    k5 <<<dim3(16, 256, 4), tb>>>(out);
}

// round 7
// speedup vs baseline: 1.8288x; 1.3977x over previous
#include <cuda_runtime.h>
#include <cuda_bf16.h>
#include <cstdint>
#include <cstddef>

#define BB 4
#define NO3 384
#define FFQ 64
#define TTT 512
#define NHH 8
#define HDD 1024
#define CF 8192
#define EPSV 1e-5f

// ---------------- scratch ----------------
__device__ float g_xt [BB*TTT*CF];
__device__ float g_v  [BB*NHH*TTT*HDD];
__device__ float g_s  [BB*NHH*TTT*TTT];
__device__ float g_ctx[BB*NHH*TTT*HDD];
__device__ float g_c  [BB*128*TTT*FFQ];
__device__ float g_y  [BB*TTT*CF];
__device__ __nv_bfloat16 g_wqhb[NO3*128], g_wqlb[NO3*128];
__device__ __nv_bfloat16 g_wphb[128*128], g_wplb[128*128];
__device__ __nv_bfloat16 g_qh[BB*NHH*TTT*HDD];
__device__ __nv_bfloat16 g_ql[BB*NHH*TTT*HDD];
__device__ __nv_bfloat16 g_kh[BB*NHH*TTT*HDD];
__device__ __nv_bfloat16 g_kl[BB*NHH*TTT*HDD];
__device__ __nv_bfloat16 g_vth[BB*NHH*HDD*TTT];
__device__ __nv_bfloat16 g_vtl[BB*NHH*HDD*TTT];
__device__ __nv_bfloat16 g_ph[BB*NHH*TTT*TTT];
__device__ __nv_bfloat16 g_pl[BB*NHH*TTT*TTT];

// ---------------- warp-mma helpers ----------------
__device__ __forceinline__ uint32_t smem_u32(const void* p) {
    uint32_t a;
    asm("{ .reg .u64 t; cvta.to.shared.u64 t, %1; cvt.u32.u64 %0, t; }" : "=r"(a) : "l"(p));
    return a;
}
__device__ __forceinline__ void ldsm4(uint32_t* r, uint32_t a) {
    asm volatile("ldmatrix.sync.aligned.m8n8.x4.shared.b16 {%0,%1,%2,%3}, [%4];"
        : "=r"(r[0]), "=r"(r[1]), "=r"(r[2]), "=r"(r[3]) : "r"(a));
}
__device__ __forceinline__ void mmabf(float* c, const uint32_t* a, const uint32_t* b) {
    asm volatile("mma.sync.aligned.m16n8k16.row.col.f32.bf16.bf16.f32 "
        "{%0,%1,%2,%3}, {%4,%5,%6,%7}, {%8,%9}, {%0,%1,%2,%3};"
        : "+f"(c[0]), "+f"(c[1]), "+f"(c[2]), "+f"(c[3])
        : "r"(a[0]), "r"(a[1]), "r"(a[2]), "r"(a[3]), "r"(b[0]), "r"(b[1]));
}
__device__ __forceinline__ void split_bf(float f, __nv_bfloat16& h, __nv_bfloat16& l) {
    h = __float2bfloat16(f);
    l = __float2bfloat16(f - __bfloat162float(h));
}

// attention tiles: 128x64 bf16, stride 72
#define SROW 72
#define STILE (128*SROW)
#define SMEMSZ (4*STILE*2)
// conv tiles: rows x 128 bf16, stride 136
#define SROWK 136

// C[128,128] += (Ah+Al)(Bh+Bl)^T over k in [0,kmax)
template<bool MASK>
__device__ __forceinline__ void mma_core(
    const __nv_bfloat16* __restrict__ Ah, const __nv_bfloat16* __restrict__ Al, int lda,
    const __nv_bfloat16* __restrict__ Bh, const __nv_bfloat16* __restrict__ Bl, int ldb,
    int kmax, float* __restrict__ outp, int ldo, int row0, int col0, float scale)
{
    extern __shared__ __align__(16) __nv_bfloat16 sm[];
    __nv_bfloat16* sAh = sm;
    __nv_bfloat16* sAl = sm + STILE;
    __nv_bfloat16* sBh = sm + 2*STILE;
    __nv_bfloat16* sBl = sm + 3*STILE;
    uint32_t uAh = smem_u32(sAh), uAl = smem_u32(sAl);
    uint32_t uBh = smem_u32(sBh), uBl = smem_u32(sBl);

    int tid = threadIdx.x, lane = tid & 31, wid = tid >> 5;
    int wm = wid >> 2, wn = wid & 3;

    float acc[4][4][4];
    #pragma unroll
    for (int i = 0; i < 4; ++i)
        #pragma unroll
        for (int j = 0; j < 4; ++j)
            #pragma unroll
            for (int q = 0; q < 4; ++q) acc[i][j][q] = 0.f;

    uint32_t aoff = (uint32_t)(((wm*64 + (lane & 15))*SROW + (lane >> 4)*8) * 2);
    uint32_t boff = (uint32_t)(((wn*32 + ((lane & 7) + ((lane >> 4) << 3)))*SROW + ((lane >> 3) & 1)*8) * 2);

    for (int k0 = 0; k0 < kmax; k0 += 64) {
        __syncthreads();
        #pragma unroll
        for (int j = 0; j < 4; ++j) {
            int ii = j*256 + tid;
            int r = ii >> 3, c = (ii & 7) << 3;
            *(uint4*)(sAh + r*SROW + c) = *(const uint4*)(Ah + (size_t)r*lda + k0 + c);
            *(uint4*)(sAl + r*SROW + c) = *(const uint4*)(Al + (size_t)r*lda + k0 + c);
            *(uint4*)(sBh + r*SROW + c) = *(const uint4*)(Bh + (size_t)r*ldb + k0 + c);
            *(uint4*)(sBl + r*SROW + c) = *(const uint4*)(Bl + (size_t)r*ldb + k0 + c);
        }
        __syncthreads();
        #pragma unroll
        for (int kk = 0; kk < 4; ++kk) {
            uint32_t bh[4][2], bl[4][2];
            #pragma unroll
            for (int ng = 0; ng < 2; ++ng) {
                uint32_t r4[4];
                ldsm4(r4, uBh + boff + ng*(16*SROW*2) + kk*32);
                bh[ng*2][0] = r4[0]; bh[ng*2][1] = r4[1];
                bh[ng*2+1][0] = r4[2]; bh[ng*2+1][1] = r4[3];
                ldsm4(r4, uBl + boff + ng*(16*SROW*2) + kk*32);
                bl[ng*2][0] = r4[0]; bl[ng*2][1] = r4[1];
                bl[ng*2+1][0] = r4[2]; bl[ng*2+1][1] = r4[3];
            }
            #pragma unroll
            for (int mf = 0; mf < 4; ++mf) {
                uint32_t ah[4], al[4];
                ldsm4(ah, uAh + aoff + mf*(16*SROW*2) + kk*32);
                ldsm4(al, uAl + aoff + mf*(16*SROW*2) + kk*32);
                #pragma unroll
                for (int nf = 0; nf < 4; ++nf) {
                    mmabf(acc[mf][nf], ah, bh[nf]);
                    mmabf(acc[mf][nf], ah, bl[nf]);
                    mmabf(acc[mf][nf], al, bh[nf]);
                }
            }
        }
    }

    int rloc0 = wm*64 + (lane >> 2);
    int cloc  = wn*32 + (lane & 3)*2;
    #pragma unroll
    for (int mf = 0; mf < 4; ++mf) {
        #pragma unroll
        for (int nf = 0; nf < 4; ++nf) {
            int cc = cloc + nf*8;
            int cg = col0 + cc;
            #pragma unroll
            for (int h = 0; h < 2; ++h) {
                int rl = rloc0 + mf*16 + h*8;
                int rg = row0 + rl;
                float v0 = acc[mf][nf][2*h], v1 = acc[mf][nf][2*h+1];
                if (MASK) {
                    v0 = (cg     <= rg) ? v0*scale : -1e30f;
                    v1 = (cg + 1 <= rg) ? v1*scale : -1e30f;
                }
                *(float2*)(outp + (size_t)rl*ldo + cc) = make_float2(v0, v1);
            }
        }
    }
}

// ---- split weights to bf16 hi/lo (native [o][c] layout = mma B [n][k]) ----
__global__ void kW(const float* __restrict__ qw, const float* __restrict__ pw) {
    int i = blockIdx.x * 256 + threadIdx.x;
    if (i < NO3*128) {
        __nv_bfloat16 h, l; split_bf(qw[i], h, l);
        g_wqhb[i] = h; g_wqlb[i] = l;
    }
    if (i < 128*128) {
        __nv_bfloat16 h, l; split_bf(pw[i], h, l);
        g_wphb[i] = h; g_wplb[i] = l;
    }
}

// ---- x [b][cf][t] -> g_xt [b][t][cf] ----
__global__ void k0(const float* __restrict__ x) {
    __shared__ float tl[32][33];
    int b = blockIdx.z, t0 = blockIdx.x*32, r0 = blockIdx.y*32;
    const float* xb = x + (size_t)b*CF*TTT;
    for (int i = threadIdx.y; i < 32; i += 8)
        tl[i][threadIdx.x] = xb[(size_t)(r0+i)*TTT + t0 + threadIdx.x];
    __syncthreads();
    float* d = g_xt + (size_t)b*TTT*CF;
    for (int i = threadIdx.y; i < 32; i += 8)
        d[(size_t)(t0+i)*CF + r0 + threadIdx.x] = tl[threadIdx.x][i];
}

// ==== k1: QKV conv (mma) + PReLU + LN + head scatter; block per (b,t) ====
// A[f=64][c=128] split-bf16; B = W[o=384][c=128] split-bf16 in 3 N-chunks of 128.
#define K1_SAH 0
#define K1_SAL 17408
#define K1_SWH 34816
#define K1_SWL 69632
#define K1_SY  104448
#define K1_SMEM (104448 + 98304)
__global__ __launch_bounds__(256) void k1(
    const float* __restrict__ bias, const float* __restrict__ alp,
    const float* __restrict__ gam,  const float* __restrict__ bet)
{
    extern __shared__ __align__(16) uint8_t sm1[];
    __nv_bfloat16* sAh = (__nv_bfloat16*)(sm1 + K1_SAH);
    __nv_bfloat16* sAl = (__nv_bfloat16*)(sm1 + K1_SAL);
    __nv_bfloat16* sWh = (__nv_bfloat16*)(sm1 + K1_SWH);
    __nv_bfloat16* sWl = (__nv_bfloat16*)(sm1 + K1_SWL);
    float* sY = (float*)(sm1 + K1_SY);
    __shared__ float r1[256], r2[256];
    uint32_t uAh = smem_u32(sAh), uAl = smem_u32(sAl);
    uint32_t uWh = smem_u32(sWh), uWl = smem_u32(sWl);

    int tid = threadIdx.x, lane = tid & 31, wid = tid >> 5;
    int wm = wid >> 2, wn = wid & 3;
    int t = blockIdx.x, b = blockIdx.y;

    // load x row [c*64+f], convert to A[f][c] hi/lo
    const float4* xr = (const float4*)(g_xt + ((size_t)b*TTT + t)*CF);
    #pragma unroll
    for (int k = 0; k < 8; ++k) {
        int i4 = tid + k*256;
        float4 v = xr[i4];
        int c = i4 >> 4, f0 = (i4 & 15) * 4;
        float vv[4] = {v.x, v.y, v.z, v.w};
        #pragma unroll
        for (int j = 0; j < 4; ++j) {
            __nv_bfloat16 h, l; split_bf(vv[j], h, l);
            sAh[(f0+j)*SROWK + c] = h;
            sAl[(f0+j)*SROWK + c] = l;
        }
    }

    float acc[3][2][4][4];
    #pragma unroll
    for (int a = 0; a < 3; ++a)
        #pragma unroll
        for (int i = 0; i < 2; ++i)
            #pragma unroll
            for (int j = 0; j < 4; ++j)
                #pragma unroll
                for (int q = 0; q < 4; ++q) acc[a][i][j][q] = 0.f;

    uint32_t aoff = (uint32_t)(((wm*32 + (lane & 15))*SROWK + (lane >> 4)*8) * 2);
    uint32_t boff = (uint32_t)(((wn*32 + ((lane & 7) + ((lane >> 4) << 3)))*SROWK + ((lane >> 3) & 1)*8) * 2);

    #pragma unroll
    for (int nc = 0; nc < 3; ++nc) {
        __syncthreads();
        const uint4* wh4 = (const uint4*)(g_wqhb + nc*128*128);
        const uint4* wl4 = (const uint4*)(g_wqlb + nc*128*128);
        #pragma unroll
        for (int k = 0; k < 8; ++k) {
            int i = tid + k*256;
            int r = i >> 4, c8 = (i & 15) << 3;
            *(uint4*)(sWh + r*SROWK + c8) = wh4[i];
            *(uint4*)(sWl + r*SROWK + c8) = wl4[i];
        }
        __syncthreads();
        #pragma unroll
        for (int kk = 0; kk < 8; ++kk) {
            uint32_t bhf[4][2], blf[4][2];
            #pragma unroll
            for (int ng = 0; ng < 2; ++ng) {
                uint32_t r4[4];
                ldsm4(r4, uWh + boff + ng*(16*SROWK*2) + kk*32);
                bhf[ng*2][0] = r4[0]; bhf[ng*2][1] = r4[1];
                bhf[ng*2+1][0] = r4[2]; bhf[ng*2+1][1] = r4[3];
                ldsm4(r4, uWl + boff + ng*(16*SROWK*2) + kk*32);
                blf[ng*2][0] = r4[0]; blf[ng*2][1] = r4[1];
                blf[ng*2+1][0] = r4[2]; blf[ng*2+1][1] = r4[3];
            }
            #pragma unroll
            for (int mf = 0; mf < 2; ++mf) {
                uint32_t ah[4], al[4];
                ldsm4(ah, uAh + aoff + mf*(16*SROWK*2) + kk*32);
                ldsm4(al, uAl + aoff + mf*(16*SROWK*2) + kk*32);
                #pragma unroll
                for (int nf = 0; nf < 4; ++nf) {
                    mmabf(acc[nc][mf][nf], ah, bhf[nf]);
                    mmabf(acc[nc][mf][nf], ah, blf[nf]);
                    mmabf(acc[nc][mf][nf], al, bhf[nf]);
                }
            }
        }
    }

    // bias + PReLU + local stats
    float alpha = alp[0];
    float ls = 0.f, lq = 0.f;
    #pragma unroll
    for (int nc = 0; nc < 3; ++nc)
        #pragma unroll
        for (int mf = 0; mf < 2; ++mf)
            #pragma unroll
            for (int nf = 0; nf < 4; ++nf) {
                int o0 = nc*128 + wn*32 + nf*8 + (lane & 3)*2;
                float b0 = bias[o0], b1 = bias[o0+1];
                #pragma unroll
                for (int h = 0; h < 2; ++h) {
                    float v0 = acc[nc][mf][nf][2*h] + b0;
                    float v1 = acc[nc][mf][nf][2*h+1] + b1;
                    v0 = v0 >= 0.f ? v0 : alpha*v0;
                    v1 = v1 >= 0.f ? v1 : alpha*v1;
                    acc[nc][mf][nf][2*h] = v0; acc[nc][mf][nf][2*h+1] = v1;
                    ls += v0 + v1; lq += v0*v0 + v1*v1;
                }
            }
    r1[tid] = ls; r2[tid] = lq;
    __syncthreads();
    for (int s = 128; s > 0; s >>= 1) {
        if (tid < s) { r1[tid] += r1[tid+s]; r2[tid] += r2[tid+s]; }
        __syncthreads();
    }
    const float invN = 1.f / (float)(NO3*FFQ);
    float mu = r1[0]*invN, var = r2[0]*invN - mu*mu;
    float rstd = rsqrtf(var + EPSV);

    // normalize + write y to smem [o][f]
    #pragma unroll
    for (int nc = 0; nc < 3; ++nc)
        #pragma unroll
        for (int mf = 0; mf < 2; ++mf)
            #pragma unroll
            for (int nf = 0; nf < 4; ++nf) {
                int o0 = nc*128 + wn*32 + nf*8 + (lane & 3)*2;
                #pragma unroll
                for (int h = 0; h < 2; ++h) {
                    int f = wm*32 + mf*16 + h*8 + (lane >> 2);
                    int gi0 = o0*64 + f, gi1 = gi0 + 64;
                    sY[gi0] = (acc[nc][mf][nf][2*h]   - mu)*rstd*gam[gi0] + bet[gi0];
                    sY[gi1] = (acc[nc][mf][nf][2*h+1] - mu)*rstd*gam[gi1] + bet[gi1];
                }
            }
    __syncthreads();

    // scatter to q/k/v (verified epilogue)
    int to = tid >> 3, tf = tid & 7;
    #pragma unroll
    for (int r = 0; r < 12; ++r) {
        int o = to*12 + r;
        int h = o / 48, rem = o % 48;
        int which = rem >> 4, dc = rem & 15;
        size_t base = (((size_t)b*NHH + h)*TTT + t)*HDD + dc*FFQ + (tf << 3);
        float ov[8];
        *(float4*)(ov)     = *(const float4*)(sY + o*64 + (tf << 3));
        *(float4*)(ov + 4) = *(const float4*)(sY + o*64 + (tf << 3) + 4);
        if (which == 2) {
            *(float4*)(g_v + base)     = *(float4*)(ov);
            *(float4*)(g_v + base + 4) = *(float4*)(ov + 4);
        } else {
            __nv_bfloat16* dh = (which == 0) ? g_qh : g_kh;
            __nv_bfloat16* dl = (which == 0) ? g_ql : g_kl;
            uint32_t hp[4], lp[4];
            #pragma unroll
            for (int p = 0; p < 4; ++p) {
                __nv_bfloat16 h0, l0, h1, l1;
                split_bf(ov[2*p], h0, l0);
                split_bf(ov[2*p+1], h1, l1);
                hp[p] = (uint32_t)__bfloat16_as_ushort(h0) | ((uint32_t)__bfloat16_as_ushort(h1) << 16);
                lp[p] = (uint32_t)__bfloat16_as_ushort(l0) | ((uint32_t)__bfloat16_as_ushort(l1) << 16);
            }
            *(uint4*)(dh + base) = *(uint4*)hp;
            *(uint4*)(dl + base) = *(uint4*)lp;
        }
    }
}

// ---- V transpose + split ----
__global__ void k1v() {
    __shared__ float tl[32][33];
    int bh = blockIdx.z, t0 = blockIdx.x*32, d0 = blockIdx.y*32;
    const float* src = g_v + (size_t)bh*TTT*HDD;
    for (int i = threadIdx.y; i < 32; i += 8)
        tl[i][threadIdx.x] = src[(size_t)(t0+i)*HDD + d0 + threadIdx.x];
    __syncthreads();
    size_t ob = (size_t)bh*HDD*TTT;
    for (int i = threadIdx.y; i < 32; i += 8) {
        __nv_bfloat16 h, l; split_bf(tl[threadIdx.x][i], h, l);
        size_t o = ob + (size_t)(d0+i)*TTT + t0 + threadIdx.x;
        g_vth[o] = h; g_vtl[o] = l;
    }
}

// ---- k2a: S = QK^T /32 (causal) ----
__global__ __launch_bounds__(256) void k2a() {
    int kt = blockIdx.x, qt = blockIdx.y, bh = blockIdx.z;
    if (kt > qt) return;
    const __nv_bfloat16* Ah = g_qh + ((size_t)bh*TTT + qt*128)*HDD;
    const __nv_bfloat16* Al = g_ql + ((size_t)bh*TTT + qt*128)*HDD;
    const __nv_bfloat16* Bh = g_kh + ((size_t)bh*TTT + kt*128)*HDD;
    const __nv_bfloat16* Bl = g_kl + ((size_t)bh*TTT + kt*128)*HDD;
    float* outp = g_s + (size_t)bh*TTT*TTT + (size_t)(qt*128)*TTT + kt*128;
    mma_core<true>(Ah, Al, HDD, Bh, Bl, HDD, HDD, outp, TTT, qt*128, kt*128, 0.03125f);
}

// ---- k2b: prefix softmax -> P hi/lo bf16 ----
__global__ __launch_bounds__(256) void k2b() {
    int qi = blockIdx.x, bh = blockIdx.y;
    int n = (qi & ~127) + 128;
    const float* row = g_s + ((size_t)bh*TTT + qi)*TTT;
    __shared__ float red[256];
    int tid = threadIdx.x;
    float v0 = (tid < n)     ? row[tid]     : -1e30f;
    float v1 = (tid+256 < n) ? row[tid+256] : -1e30f;
    red[tid] = fmaxf(v0, v1); __syncthreads();
    for (int s = 128; s > 0; s >>= 1) {
        if (tid < s) red[tid] = fmaxf(red[tid], red[tid+s]);
        __syncthreads();
    }
    float m = red[0]; __syncthreads();
    float e0 = __expf(v0 - m), e1 = __expf(v1 - m);
    red[tid] = e0 + e1; __syncthreads();
    for (int s = 128; s > 0; s >>= 1) {
        if (tid < s) red[tid] += red[tid+s];
        __syncthreads();
    }
    float inv = 1.f / red[0];
    __nv_bfloat16* ph = g_ph + ((size_t)bh*TTT + qi)*TTT;
    __nv_bfloat16* pl = g_pl + ((size_t)bh*TTT + qi)*TTT;
    if (tid < n) {
        float p = e0 * inv;
        __nv_bfloat16 h, l; split_bf(p, h, l);
        ph[tid] = h; pl[tid] = l;
    }
    if (tid + 256 < n) {
        float p = e1 * inv;
        __nv_bfloat16 h, l; split_bf(p, h, l);
        ph[tid+256] = h; pl[tid+256] = l;
    }
}

// ---- k2c: ctx = P @ V ----
__global__ __launch_bounds__(256) void k2c() {
    int dt = blockIdx.x, qt = blockIdx.y, bh = blockIdx.z;
    const __nv_bfloat16* Ah = g_ph  + ((size_t)bh*TTT + qt*128)*TTT;
    const __nv_bfloat16* Al = g_pl  + ((size_t)bh*TTT + qt*128)*TTT;
    const __nv_bfloat16* Bh = g_vth + ((size_t)bh*HDD + dt*128)*TTT;
    const __nv_bfloat16* Bl = g_vtl + ((size_t)bh*HDD + dt*128)*TTT;
    float* outp = g_ctx + (size_t)bh*TTT*HDD + (size_t)(qt*128)*HDD + dt*128;
    mma_core<false>(Ah, Al, TTT, Bh, Bl, TTT, (qt + 1)*128, outp, HDD, 0, 0, 1.f);
}

// ---- ctx remap ----
__global__ void k3() {
    __shared__ float tl[32][33];
    int bhdc = blockIdx.z, bh = bhdc >> 4, dc = bhdc & 15;
    int t0 = blockIdx.x*32, d0 = blockIdx.y*32;
    const float* src = g_ctx + (size_t)bh*TTT*HDD + dc*64;
    for (int i = threadIdx.y; i < 32; i += 8)
        tl[i][threadIdx.x] = src[(size_t)(t0+i)*HDD + d0 + threadIdx.x];
    __syncthreads();
    float* dst = g_c + (size_t)bhdc*TTT*FFQ;
    for (int i = threadIdx.y; i < 32; i += 8)
        dst[(size_t)(d0+i)*TTT + t0 + threadIdx.x] = tl[threadIdx.x][i];
}

// ==== k4: proj conv (mma) + PReLU + LN; block per (b,t2) ====
#define K4_SY 104448
#define K4_SMEM (104448 + 32768)
__global__ __launch_bounds__(256) void k4(
    const float* __restrict__ bias, const float* __restrict__ alp,
    const float* __restrict__ gam,  const float* __restrict__ bet)
{
    extern __shared__ __align__(16) uint8_t sm4[];
    __nv_bfloat16* sAh = (__nv_bfloat16*)(sm4 + K1_SAH);
    __nv_bfloat16* sAl = (__nv_bfloat16*)(sm4 + K1_SAL);
    __nv_bfloat16* sWh = (__nv_bfloat16*)(sm4 + K1_SWH);
    __nv_bfloat16* sWl = (__nv_bfloat16*)(sm4 + K1_SWL);
    float* sY = (float*)(sm4 + K4_SY);
    __shared__ float r1[256], r2[256];
    uint32_t uAh = smem_u32(sAh), uAl = smem_u32(sAl);
    uint32_t uWh = smem_u32(sWh), uWl = smem_u32(sWl);

    int tid = threadIdx.x, lane = tid & 31, wid = tid >> 5;
    int wm = wid >> 2, wn = wid & 3;
    int t2 = blockIdx.x, b = blockIdx.y;

    // gather A[f][c] from g_c[(b*128+c)][t2][f]
    {
        int c = tid >> 1, half = tid & 1;
        const float4* sp = (const float4*)(g_c + (((size_t)(b*128 + c))*TTT + t2)*FFQ + half*32);
        #pragma unroll
        for (int j = 0; j < 8; ++j) {
            float4 v = sp[j];
            int f0 = half*32 + j*4;
            float vv[4] = {v.x, v.y, v.z, v.w};
            #pragma unroll
            for (int jj = 0; jj < 4; ++jj) {
                __nv_bfloat16 h, l; split_bf(vv[jj], h, l);
                sAh[(f0+jj)*SROWK + c] = h;
                sAl[(f0+jj)*SROWK + c] = l;
            }
        }
    }
    // stage W
    {
        const uint4* wh4 = (const uint4*)g_wphb;
        const uint4* wl4 = (const uint4*)g_wplb;
        #pragma unroll
        for (int k = 0; k < 8; ++k) {
            int i = tid + k*256;
            int r = i >> 4, c8 = (i & 15) << 3;
            *(uint4*)(sWh + r*SROWK + c8) = wh4[i];
            *(uint4*)(sWl + r*SROWK + c8) = wl4[i];
        }
    }
    __syncthreads();

    float acc[2][4][4];
    #pragma unroll
    for (int i = 0; i < 2; ++i)
        #pragma unroll
        for (int j = 0; j < 4; ++j)
            #pragma unroll
            for (int q = 0; q < 4; ++q) acc[i][j][q] = 0.f;

    uint32_t aoff = (uint32_t)(((wm*32 + (lane & 15))*SROWK + (lane >> 4)*8) * 2);
    uint32_t boff = (uint32_t)(((wn*32 + ((lane & 7) + ((lane >> 4) << 3)))*SROWK + ((lane >> 3) & 1)*8) * 2);

    #pragma unroll
    for (int kk = 0; kk < 8; ++kk) {
        uint32_t bhf[4][2], blf[4][2];
        #pragma unroll
        for (int ng = 0; ng < 2; ++ng) {
            uint32_t r4[4];
            ldsm4(r4, uWh + boff + ng*(16*SROWK*2) + kk*32);
            bhf[ng*2][0] = r4[0]; bhf[ng*2][1] = r4[1];
            bhf[ng*2+1][0] = r4[2]; bhf[ng*2+1][1] = r4[3];
            ldsm4(r4, uWl + boff + ng*(16*SROWK*2) + kk*32);
            blf[ng*2][0] = r4[0]; blf[ng*2][1] = r4[1];
            blf[ng*2+1][0] = r4[2]; blf[ng*2+1][1] = r4[3];
        }
        #pragma unroll
        for (int mf = 0; mf < 2; ++mf) {
            uint32_t ah[4], al[4];
            ldsm4(ah, uAh + aoff + mf*(16*SROWK*2) + kk*32);
            ldsm4(al, uAl + aoff + mf*(16*SROWK*2) + kk*32);
            #pragma unroll
            for (int nf = 0; nf < 4; ++nf) {
                mmabf(acc[mf][nf], ah, bhf[nf]);
                mmabf(acc[mf][nf], ah, blf[nf]);
                mmabf(acc[mf][nf], al, bhf[nf]);
            }
        }
    }

    float alpha = alp[0];
    float ls = 0.f, lq = 0.f;
    #pragma unroll
    for (int mf = 0; mf < 2; ++mf)
        #pragma unroll
        for (int nf = 0; nf < 4; ++nf) {
            int o0 = wn*32 + nf*8 + (lane & 3)*2;
            float b0 = bias[o0], b1 = bias[o0+1];
            #pragma unroll
            for (int h = 0; h < 2; ++h) {
                float v0 = acc[mf][nf][2*h] + b0;
                float v1 = acc[mf][nf][2*h+1] + b1;
                v0 = v0 >= 0.f ? v0 : alpha*v0;
                v1 = v1 >= 0.f ? v1 : alpha*v1;
                acc[mf][nf][2*h] = v0; acc[mf][nf][2*h+1] = v1;
                ls += v0 + v1; lq += v0*v0 + v1*v1;
            }
        }
    r1[tid] = ls; r2[tid] = lq;
    __syncthreads();
    for (int s = 128; s > 0; s >>= 1) {
        if (tid < s) { r1[tid] += r1[tid+s]; r2[tid] += r2[tid+s]; }
        __syncthreads();
    }
    const float invN = 1.f / (float)CF;
    float mu = r1[0]*invN, var = r2[0]*invN - mu*mu;
    float rstd = rsqrtf(var + EPSV);

    #pragma unroll
    for (int mf = 0; mf < 2; ++mf)
        #pragma unroll
        for (int nf = 0; nf < 4; ++nf) {
            int o0 = wn*32 + nf*8 + (lane & 3)*2;
            #pragma unroll
            for (int h = 0; h < 2; ++h) {
                int f = wm*32 + mf*16 + h*8 + (lane >> 2);
                int gi0 = o0*64 + f, gi1 = gi0 + 64;
                sY[gi0] = (acc[mf][nf][2*h]   - mu)*rstd*gam[gi0] + bet[gi0];
                sY[gi1] = (acc[mf][nf][2*h+1] - mu)*rstd*gam[gi1] + bet[gi1];
            }
        }
    __syncthreads();

    float* yrow = g_y + ((size_t)b*TTT + t2)*CF;
    const float4* sY4 = (const float4*)sY;
    float4* yr4 = (float4*)yrow;
    #pragma unroll
    for (int k = 0; k < 8; ++k) yr4[tid + k*256] = sY4[tid + k*256];
}

// ---- g_y [b][t2][cf] -> out [b][cf][t2] ----
__global__ void k5(float* __restrict__ out) {
    __shared__ float tl[32][33];
    int b = blockIdx.z, t0 = blockIdx.x*32, r0 = blockIdx.y*32;
    const float* s = g_y + (size_t)b*TTT*CF;
    for (int i = threadIdx.y; i < 32; i += 8)
        tl[i][threadIdx.x] = s[(size_t)(t0+i)*CF + r0 + threadIdx.x];
    __syncthreads();
    float* d = out + (size_t)b*CF*TTT;
    for (int i = threadIdx.y; i < 32; i += 8)
        d[(size_t)(r0+i)*TTT + t0 + threadIdx.x] = tl[threadIdx.x][i];
}

extern "C" void kernel_launch(void* const* d_in, const int* in_sizes, int n_in,
                              void* d_out, int out_size) {
    const float* x   = (const float*)d_in[0];
    const float* qw  = (const float*)d_in[1];
    const float* qb  = (const float*)d_in[2];
    const float* qa  = (const float*)d_in[3];
    const float* qg  = (const float*)d_in[4];
    const float* qbe = (const float*)d_in[5];
    const float* pw  = (const float*)d_in[6];
    const float* pb  = (const float*)d_in[7];
    const float* pa  = (const float*)d_in[8];
    const float* pg  = (const float*)d_in[9];
    const float* pbe = (const float*)d_in[10];
    float* out = (float*)d_out;

    cudaFuncSetAttribute(k1,  cudaFuncAttributeMaxDynamicSharedMemorySize, K1_SMEM);
    cudaFuncSetAttribute(k2a, cudaFuncAttributeMaxDynamicSharedMemorySize, SMEMSZ);
    cudaFuncSetAttribute(k2c, cudaFuncAttributeMaxDynamicSharedMemorySize, SMEMSZ);
    cudaFuncSetAttribute(k4,  cudaFuncAttributeMaxDynamicSharedMemorySize, K4_SMEM);

    dim3 tb(32, 8);
    kW <<<192, 256>>>(qw, pw);
    k0 <<<dim3(16, 256, 4), tb>>>(x);
    k1 <<<dim3(512, 4), 256, K1_SMEM>>>(qb, qa, qg, qbe);
    k1v<<<dim3(16, 32, 32), tb>>>();
    k2a<<<dim3(4, 4, 32), 256, SMEMSZ>>>();
    k2b<<<dim3(512, 32), 256>>>();
    k2c<<<dim3(8, 4, 32), 256, SMEMSZ>>>();
    k3 <<<dim3(16, 2, 512), tb>>>();
    k4 <<<dim3(512, 4), 256, K4_SMEM>>>(pb, pa, pg, pbe);
    k5 <<<dim3(16, 256, 4), tb>>>(out);
}